// round 16
// baseline (speedup 1.0000x reference)
#include <cuda_runtime.h>
#include <cuda_fp16.h>

#define N_NODES 100000
#define HDIM 128
#define NE 1600000
#define NGRAPH 512
#define TDIM 10

// ---------------- scratch (device globals: allocation-free) ----------------
__device__ float g_agg[(size_t)N_NODES * HDIM];
__device__ float g_t[(size_t)N_NODES * HDIM];
__device__ float g_h[(size_t)N_NODES * HDIM];
// fp16 gather operand, packed 4 halves per u64 (8B-aligned, scalar access only)
__device__ unsigned long long g_xh2[(size_t)N_NODES * (HDIM / 4)];
__device__ float g_colsum[HDIM];
__device__ float g_colsumsq[HDIM];
__device__ float g_scale[HDIM];
__device__ float g_shift[HDIM];
__device__ float g_pooled[NGRAPH * HDIM];
// CSR scratch
__device__ int g_deg[N_NODES];
__device__ int g_off[N_NODES + 1];
__device__ int g_cursor[N_NODES];
__device__ int g_srcs[NE];
__device__ int g_goff[NGRAPH + 1];

// ---------------- packed f32x2 helpers ----------------
#define PACK2F(d, lo, hi)                                            \
    asm("mov.b64 %0, {%1, %2};" : "=l"(d)                            \
        : "r"(__float_as_uint(lo)), "r"(__float_as_uint(hi)))
#define UNPACK2F(lo, hi, s)                                          \
    do {                                                             \
        unsigned _ulo, _uhi;                                         \
        asm("mov.b64 {%0, %1}, %2;" : "=r"(_ulo), "=r"(_uhi) : "l"(s)); \
        lo = __uint_as_float(_ulo); hi = __uint_as_float(_uhi);      \
    } while (0)
#define FFMA2(d, a, b, c)                                            \
    asm("fma.rn.f32x2 %0, %1, %2, %3;" : "=l"(d) : "l"(a), "l"(b), "l"(c))

// ---- scalar fp16 pack/unpack (register-only, no struct aliasing) ----
__device__ __forceinline__ unsigned long long pack4h(float4 v) {
    unsigned long long a0 = __half_as_ushort(__float2half_rn(v.x));
    unsigned long long a1 = __half_as_ushort(__float2half_rn(v.y));
    unsigned long long a2 = __half_as_ushort(__float2half_rn(v.z));
    unsigned long long a3 = __half_as_ushort(__float2half_rn(v.w));
    return a0 | (a1 << 16) | (a2 << 32) | (a3 << 48);
}
__device__ __forceinline__ void acc4h(float4& s, unsigned long long v) {
    s.x += __half2float(__ushort_as_half((unsigned short)v));
    s.y += __half2float(__ushort_as_half((unsigned short)(v >> 16)));
    s.z += __half2float(__ushort_as_half((unsigned short)(v >> 32)));
    s.w += __half2float(__ushort_as_half((unsigned short)(v >> 48)));
}

// ====== x -> fp16 conversion (one u64 = 4 floats per thread) ======
__global__ void tohalf_kernel(const float* __restrict__ x) {
    int i = blockIdx.x * blockDim.x + threadIdx.x;
    if (i >= (int)((size_t)N_NODES * (HDIM / 4))) return;
    float4 v = __ldg(reinterpret_cast<const float4*>(x) + i);
    g_xh2[i] = pack4h(v);
}

// ================= CSR build (once per launch) =================
__global__ void hist_kernel(const int* __restrict__ ei) {
    int e = blockIdx.x * blockDim.x + threadIdx.x;
    if (e >= NE) return;
    atomicAdd(&g_deg[ei[NE + e]], 1);
}

__global__ void scan_kernel() {
    __shared__ int warpsums[32];
    const int tid = threadIdx.x;
    const int lane = tid & 31, w = tid >> 5;
    const int CH = (N_NODES + 1023) / 1024;  // 98
    int start = tid * CH;
    int end = start + CH < N_NODES ? start + CH : N_NODES;
    if (start > N_NODES) start = N_NODES;
    int s = 0;
    for (int i = start; i < end; i++) s += g_deg[i];
    int v = s;
#pragma unroll
    for (int d = 1; d < 32; d <<= 1) {
        int t = __shfl_up_sync(~0u, v, d);
        if (lane >= d) v += t;
    }
    if (lane == 31) warpsums[w] = v;
    __syncthreads();
    if (w == 0) {
        int ws = warpsums[lane];
#pragma unroll
        for (int d = 1; d < 32; d <<= 1) {
            int t = __shfl_up_sync(~0u, ws, d);
            if (lane >= d) ws += t;
        }
        warpsums[lane] = ws;
    }
    __syncthreads();
    int base = (w > 0 ? warpsums[w - 1] : 0) + (v - s);
    int run = base;
    for (int i = start; i < end; i++) {
        g_off[i] = run;
        g_cursor[i] = run;
        run += g_deg[i];
    }
    if (tid == 1023) g_off[N_NODES] = run;
}

__global__ void bin_kernel(const int* __restrict__ ei) {
    int e = blockIdx.x * blockDim.x + threadIdx.x;
    if (e >= NE) return;
    int s = ei[e];
    int d = ei[NE + e];
    int pos = atomicAdd(&g_cursor[d], 1);
    g_srcs[pos] = s;
}

// parallel boundary scan over sorted batch -> g_goff (lower_bound table)
__global__ void batch_off_kernel(const int* __restrict__ batch) {
    int i = blockIdx.x * blockDim.x + threadIdx.x;
    if (i >= N_NODES) return;
    int b1 = batch[i];
    int b0 = (i == 0) ? -1 : batch[i - 1];
    for (int g = b0 + 1; g <= b1; g++) g_goff[g] = i;
    if (i == N_NODES - 1)
        for (int g = b1 + 1; g <= NGRAPH; g++) g_goff[g] = N_NODES;
}

// ====== aggregate (fp16 u64 gather): agg[n] = xh[n] + sum xh[src] ======
// one warp per node; lane owns 1 u64 = 4 cols.
// Single predicated 16-wide loop: MLP = min(deg,16) for ALL nodes (no
// low-MLP remainder path); invalid slots contribute exact +0.0f.
__global__ void __launch_bounds__(256) aggregate_kernel(float* __restrict__ agg) {
    unsigned long long tid =
        (unsigned long long)blockIdx.x * blockDim.x + threadIdx.x;
    unsigned node = (unsigned)(tid >> 5);
    if (node >= N_NODES) return;
    unsigned lane = (unsigned)tid & 31u;

    const unsigned long long* X = g_xh2;   // 32 u64 per row
    float4 sa = make_float4(0.f, 0.f, 0.f, 0.f);
    float4 sb = make_float4(0.f, 0.f, 0.f, 0.f);
    acc4h(sa, __ldg(X + (size_t)node * 32 + lane));   // self term
    const int e0 = g_off[node];
    const int e1 = g_off[node + 1];
    for (int base = e0; base < e1; base += 16) {
#pragma unroll
        for (int j = 0; j < 16; j++) {
            const int idx = base + j;
            const bool valid = idx < e1;
            int s = valid ? __ldg(g_srcs + idx) : 0;
            unsigned long long v =
                valid ? __ldg(X + (size_t)s * 32 + lane) : 0ull;
            acc4h((j & 1) ? sb : sa, v);
        }
    }
    sa.x += sb.x; sa.y += sb.y; sa.z += sb.z; sa.w += sb.w;
    reinterpret_cast<float4*>(agg + (size_t)node * HDIM)[lane] = sa;
}

// ============ pooling: contiguous segment sum (batch is sorted) ============
__global__ void pool_csr_kernel(const float* __restrict__ h) {
    int g = blockIdx.x;
    int c = threadIdx.x;
    int r = g_goff[g];
    const int r1 = g_goff[g + 1];
    float s0 = 0.f, s1 = 0.f;
    for (; r + 1 < r1; r += 2) {
        s0 += __ldg(h + (size_t)r * HDIM + c);
        s1 += __ldg(h + (size_t)(r + 1) * HDIM + c);
    }
    if (r < r1) s0 += __ldg(h + (size_t)r * HDIM + c);
    g_pooled[g * HDIM + c] = s0 + s1;
}

// ---------------- fused GEMM (col-pair f32x2, W in smem) ----------------
// MODE 0: t = A @ W + b ; accumulate col sum/sumsq
// MODE 1: h = relu( relu(A*scale+shift) @ W + b ) ; WH=1 also writes fp16 h
constexpr int WARPS = 8;
constexpr int RPW = 8;
constexpr int RPB = WARPS * RPW;     // 64 rows per block
constexpr int SMEM_FLOATS = HDIM * HDIM + WARPS * RPW * HDIM + WARPS * HDIM;
constexpr size_t SMEM_BYTES = SMEM_FLOATS * sizeof(float);  // 102400

template <int MODE, int WH>
__global__ void __launch_bounds__(256, 2) gemm_kernel(
    const float* __restrict__ A,
    const float* __restrict__ W, const float* __restrict__ bias,
    float* __restrict__ outp,
    float* __restrict__ colsum, float* __restrict__ colsumsq) {
    extern __shared__ float smem[];
    float* Wsm = smem;
    float* rowbuf = smem + HDIM * HDIM;
    float* redbuf = rowbuf + WARPS * RPW * HDIM;

    const int tid = threadIdx.x;
    const int w = tid >> 5;
    const int lane = tid & 31;

    {
        const float4* Wg4 = reinterpret_cast<const float4*>(W);
        float4* Ws4 = reinterpret_cast<float4*>(Wsm);
#pragma unroll
        for (int i = 0; i < (HDIM * HDIM / 4) / 256; i++)
            Ws4[i * 256 + tid] = __ldg(Wg4 + i * 256 + tid);
    }

    const float4 bias4 = __ldg(reinterpret_cast<const float4*>(bias) + lane);
    float4 sc4 = make_float4(0.f, 0.f, 0.f, 0.f), sh4 = sc4;
    if (MODE == 1) {
        sc4 = *(reinterpret_cast<const float4*>(g_scale) + lane);
        sh4 = *(reinterpret_cast<const float4*>(g_shift) + lane);
    }

    float* rb = rowbuf + w * (RPW * HDIM);
    const int rbase = blockIdx.x * RPB + w * RPW;

#pragma unroll
    for (int r = 0; r < RPW; r++) {
        int row = rbase + r;
        int rr = row < N_NODES ? row : N_NODES - 1;
        float4 a = __ldg(reinterpret_cast<const float4*>(A + (size_t)rr * HDIM) + lane);
        if (MODE == 1) {
            a.x = fmaxf(fmaf(a.x, sc4.x, sh4.x), 0.f);
            a.y = fmaxf(fmaf(a.y, sc4.y, sh4.y), 0.f);
            a.z = fmaxf(fmaf(a.z, sc4.z, sh4.z), 0.f);
            a.w = fmaxf(fmaf(a.w, sc4.w, sh4.w), 0.f);
        }
        reinterpret_cast<float4*>(rb + r * HDIM)[lane] = a;
    }
    __syncthreads();

    unsigned long long accL[RPW], accH[RPW];
    {
        unsigned long long blo, bhi;
        PACK2F(blo, bias4.x, bias4.y);
        PACK2F(bhi, bias4.z, bias4.w);
#pragma unroll
        for (int r = 0; r < RPW; r++) { accL[r] = blo; accH[r] = bhi; }
    }

    const float4* Ws4 = reinterpret_cast<const float4*>(Wsm);
#pragma unroll 4
    for (int k0 = 0; k0 < HDIM / 4; k0++) {
        float4 av[RPW];
#pragma unroll
        for (int r = 0; r < RPW; r++)
            av[r] = reinterpret_cast<const float4*>(rb + r * HDIM)[k0];
#pragma unroll
        for (int s4 = 0; s4 < 4; s4++) {
            const float4 wv = Ws4[(4 * k0 + s4) * 32 + lane];
            unsigned long long wlo, whi;
            PACK2F(wlo, wv.x, wv.y);
            PACK2F(whi, wv.z, wv.w);
#pragma unroll
            for (int r = 0; r < RPW; r++) {
                const float a = (s4 == 0) ? av[r].x
                              : (s4 == 1) ? av[r].y
                              : (s4 == 2) ? av[r].z : av[r].w;
                unsigned long long a2;
                PACK2F(a2, a, a);
                FFMA2(accL[r], a2, wlo, accL[r]);
                FFMA2(accH[r], a2, whi, accH[r]);
            }
        }
    }

    float s0 = 0.f, s1 = 0.f, s2 = 0.f, s3 = 0.f;
    float q0 = 0.f, q1 = 0.f, q2 = 0.f, q3 = 0.f;
#pragma unroll
    for (int r = 0; r < RPW; r++) {
        int row = rbase + r;
        if (row < N_NODES) {
            float4 c;
            UNPACK2F(c.x, c.y, accL[r]);
            UNPACK2F(c.z, c.w, accH[r]);
            if (MODE == 1) {
                c.x = fmaxf(c.x, 0.f); c.y = fmaxf(c.y, 0.f);
                c.z = fmaxf(c.z, 0.f); c.w = fmaxf(c.w, 0.f);
            }
            reinterpret_cast<float4*>(outp + (size_t)row * HDIM)[lane] = c;
            if (WH)
                g_xh2[(size_t)row * 32 + lane] = pack4h(c);
            if (MODE == 0) {
                s0 += c.x; s1 += c.y; s2 += c.z; s3 += c.w;
                q0 += c.x * c.x; q1 += c.y * c.y;
                q2 += c.z * c.z; q3 += c.w * c.w;
            }
        }
    }

    if (MODE == 0) {
        float* rw = redbuf + w * HDIM + 4 * lane;
        rw[0] = s0; rw[1] = s1; rw[2] = s2; rw[3] = s3;
        __syncthreads();
        if (tid < HDIM) {
            float t = 0.f;
#pragma unroll
            for (int ww = 0; ww < WARPS; ww++) t += redbuf[ww * HDIM + tid];
            atomicAdd(&colsum[tid], t);
        }
        __syncthreads();
        rw[0] = q0; rw[1] = q1; rw[2] = q2; rw[3] = q3;
        __syncthreads();
        if (tid < HDIM) {
            float t = 0.f;
#pragma unroll
            for (int ww = 0; ww < WARPS; ww++) t += redbuf[ww * HDIM + tid];
            atomicAdd(&colsumsq[tid], t);
        }
    }
}

// ---------------- BN finalize ----------------
__global__ void bn_finalize(const float* __restrict__ gamma,
                            const float* __restrict__ beta) {
    int i = threadIdx.x;
    const float invn = 1.0f / (float)N_NODES;
    float m = g_colsum[i] * invn;
    float v = g_colsumsq[i] * invn - m * m;
    float istd = rsqrtf(v + 1e-5f);
    float sc = istd * gamma[i];
    g_scale[i] = sc;
    g_shift[i] = beta[i] - m * sc;
}

// ---------------- classifier ----------------
__global__ void final_kernel(const float* __restrict__ Wl,
                             const float* __restrict__ bl,
                             float* __restrict__ out) {
    int g = blockIdx.x * blockDim.x + threadIdx.x;
    if (g >= NGRAPH) return;
    float acc[TDIM];
#pragma unroll
    for (int t = 0; t < TDIM; t++) acc[t] = __ldg(&bl[t]);
    const float* p = g_pooled + (size_t)g * HDIM;
#pragma unroll 8
    for (int k = 0; k < HDIM; k++) {
        float pv = p[k];
#pragma unroll
        for (int t = 0; t < TDIM; t++)
            acc[t] = fmaf(pv, __ldg(&Wl[k * TDIM + t]), acc[t]);
    }
#pragma unroll
    for (int t = 0; t < TDIM; t++) out[g * TDIM + t] = acc[t];
}

// ---------------- launch ----------------
extern "C" void kernel_launch(void* const* d_in, const int* in_sizes, int n_in,
                              void* d_out, int out_size) {
    const float* x = (const float*)d_in[0];
    const int* ei = (const int*)d_in[1];
    const int* batch = (const int*)d_in[2];
    const float* W1a = (const float*)d_in[3];
    const float* b1a = (const float*)d_in[4];
    const float* g1  = (const float*)d_in[5];
    const float* bt1 = (const float*)d_in[6];
    const float* W1b = (const float*)d_in[7];
    const float* b1b = (const float*)d_in[8];
    const float* W2a = (const float*)d_in[9];
    const float* b2a = (const float*)d_in[10];
    const float* g2  = (const float*)d_in[11];
    const float* bt2 = (const float*)d_in[12];
    const float* W2b = (const float*)d_in[13];
    const float* b2b = (const float*)d_in[14];
    const float* Wl  = (const float*)d_in[15];
    const float* bl  = (const float*)d_in[16];
    float* out = (float*)d_out;

    float *aggp, *tp, *hp, *csp, *cqp;
    int* degp;
    cudaGetSymbolAddress((void**)&aggp, g_agg);
    cudaGetSymbolAddress((void**)&tp, g_t);
    cudaGetSymbolAddress((void**)&hp, g_h);
    cudaGetSymbolAddress((void**)&csp, g_colsum);
    cudaGetSymbolAddress((void**)&cqp, g_colsumsq);
    cudaGetSymbolAddress((void**)&degp, g_deg);

    cudaFuncSetAttribute(gemm_kernel<0, 0>,
                         cudaFuncAttributeMaxDynamicSharedMemorySize,
                         (int)SMEM_BYTES);
    cudaFuncSetAttribute(gemm_kernel<1, 0>,
                         cudaFuncAttributeMaxDynamicSharedMemorySize,
                         (int)SMEM_BYTES);
    cudaFuncSetAttribute(gemm_kernel<1, 1>,
                         cudaFuncAttributeMaxDynamicSharedMemorySize,
                         (int)SMEM_BYTES);

    const int EDGE_BLOCKS = (NE + 255) / 256;
    const int NODE_BLOCKS = (N_NODES + 255) / 256;
    const int AGG_BLOCKS = (int)(((long long)N_NODES * 32 + 255) / 256);
    const int CONV_BLOCKS = (int)(((size_t)N_NODES * (HDIM / 4) + 255) / 256);
    const int GEMM_BLOCKS = (N_NODES + RPB - 1) / RPB;  // 1563

    // ---- fp16 operand + CSR build ----
    tohalf_kernel<<<CONV_BLOCKS, 256>>>(x);
    cudaMemsetAsync(degp, 0, N_NODES * sizeof(int));
    hist_kernel<<<EDGE_BLOCKS, 256>>>(ei);
    scan_kernel<<<1, 1024>>>();
    bin_kernel<<<EDGE_BLOCKS, 256>>>(ei);
    batch_off_kernel<<<NODE_BLOCKS, 256>>>(batch);

    // ---- GIN layer 1 ----
    aggregate_kernel<<<AGG_BLOCKS, 256>>>(aggp);
    cudaMemsetAsync(csp, 0, HDIM * sizeof(float));
    cudaMemsetAsync(cqp, 0, HDIM * sizeof(float));
    gemm_kernel<0, 0><<<GEMM_BLOCKS, 256, SMEM_BYTES>>>(aggp, W1a, b1a, tp, csp, cqp);
    bn_finalize<<<1, HDIM>>>(g1, bt1);
    gemm_kernel<1, 1><<<GEMM_BLOCKS, 256, SMEM_BYTES>>>(tp, W1b, b1b, hp, nullptr, nullptr);

    // ---- GIN layer 2 (aggregate reads fp16 h written by gemm<1,1>) ----
    aggregate_kernel<<<AGG_BLOCKS, 256>>>(aggp);
    cudaMemsetAsync(csp, 0, HDIM * sizeof(float));
    cudaMemsetAsync(cqp, 0, HDIM * sizeof(float));
    gemm_kernel<0, 0><<<GEMM_BLOCKS, 256, SMEM_BYTES>>>(aggp, W2a, b2a, tp, csp, cqp);
    bn_finalize<<<1, HDIM>>>(g2, bt2);
    gemm_kernel<1, 0><<<GEMM_BLOCKS, 256, SMEM_BYTES>>>(tp, W2b, b2b, hp, nullptr, nullptr);

    // ---- pool + classifier ----
    pool_csr_kernel<<<NGRAPH, HDIM>>>(hp);
    final_kernel<<<(NGRAPH + 255) / 256, 256>>>(Wl, bl, out);
}

// round 17
// speedup vs baseline: 1.0776x; 1.0776x over previous
#include <cuda_runtime.h>
#include <cuda_fp16.h>

#define N_NODES 100000
#define HDIM 128
#define NE 1600000
#define NGRAPH 512
#define TDIM 10

// ---------------- scratch (device globals: allocation-free) ----------------
__device__ float g_agg[(size_t)N_NODES * HDIM];
__device__ float g_t[(size_t)N_NODES * HDIM];
__device__ float g_h[(size_t)N_NODES * HDIM];
// fp16 gather operand, packed 4 halves per u64 (8B-aligned, scalar access only)
__device__ unsigned long long g_xh2[(size_t)N_NODES * (HDIM / 4)];
__device__ float g_colsum[HDIM];
__device__ float g_colsumsq[HDIM];
__device__ float g_scale[HDIM];
__device__ float g_shift[HDIM];
__device__ float g_pooled[NGRAPH * HDIM];
// CSR scratch
__device__ int g_deg[N_NODES];
__device__ int g_off[N_NODES + 1];
__device__ int g_cursor[N_NODES];
__device__ int g_srcs[NE];
__device__ int g_goff[NGRAPH + 1];

// ---------------- packed f32x2 helpers ----------------
#define PACK2F(d, lo, hi)                                            \
    asm("mov.b64 %0, {%1, %2};" : "=l"(d)                            \
        : "r"(__float_as_uint(lo)), "r"(__float_as_uint(hi)))
#define UNPACK2F(lo, hi, s)                                          \
    do {                                                             \
        unsigned _ulo, _uhi;                                         \
        asm("mov.b64 {%0, %1}, %2;" : "=r"(_ulo), "=r"(_uhi) : "l"(s)); \
        lo = __uint_as_float(_ulo); hi = __uint_as_float(_uhi);      \
    } while (0)
#define FFMA2(d, a, b, c)                                            \
    asm("fma.rn.f32x2 %0, %1, %2, %3;" : "=l"(d) : "l"(a), "l"(b), "l"(c))

// ---- scalar fp16 pack/unpack (register-only, no struct aliasing) ----
__device__ __forceinline__ unsigned long long pack4h(float4 v) {
    unsigned long long a0 = __half_as_ushort(__float2half_rn(v.x));
    unsigned long long a1 = __half_as_ushort(__float2half_rn(v.y));
    unsigned long long a2 = __half_as_ushort(__float2half_rn(v.z));
    unsigned long long a3 = __half_as_ushort(__float2half_rn(v.w));
    return a0 | (a1 << 16) | (a2 << 32) | (a3 << 48);
}
__device__ __forceinline__ void acc4h(float4& s, unsigned long long v) {
    s.x += __half2float(__ushort_as_half((unsigned short)v));
    s.y += __half2float(__ushort_as_half((unsigned short)(v >> 16)));
    s.z += __half2float(__ushort_as_half((unsigned short)(v >> 32)));
    s.w += __half2float(__ushort_as_half((unsigned short)(v >> 48)));
}

// ====== x -> fp16 conversion (one u64 = 4 floats per thread) ======
__global__ void tohalf_kernel(const float* __restrict__ x) {
    int i = blockIdx.x * blockDim.x + threadIdx.x;
    if (i >= (int)((size_t)N_NODES * (HDIM / 4))) return;
    float4 v = __ldg(reinterpret_cast<const float4*>(x) + i);
    g_xh2[i] = pack4h(v);
}

// ================= CSR build (once per launch) =================
__global__ void hist_kernel(const int* __restrict__ ei) {
    int e = blockIdx.x * blockDim.x + threadIdx.x;
    if (e >= NE) return;
    atomicAdd(&g_deg[ei[NE + e]], 1);
}

__global__ void scan_kernel() {
    __shared__ int warpsums[32];
    const int tid = threadIdx.x;
    const int lane = tid & 31, w = tid >> 5;
    const int CH = (N_NODES + 1023) / 1024;  // 98
    int start = tid * CH;
    int end = start + CH < N_NODES ? start + CH : N_NODES;
    if (start > N_NODES) start = N_NODES;
    int s = 0;
    for (int i = start; i < end; i++) s += g_deg[i];
    int v = s;
#pragma unroll
    for (int d = 1; d < 32; d <<= 1) {
        int t = __shfl_up_sync(~0u, v, d);
        if (lane >= d) v += t;
    }
    if (lane == 31) warpsums[w] = v;
    __syncthreads();
    if (w == 0) {
        int ws = warpsums[lane];
#pragma unroll
        for (int d = 1; d < 32; d <<= 1) {
            int t = __shfl_up_sync(~0u, ws, d);
            if (lane >= d) ws += t;
        }
        warpsums[lane] = ws;
    }
    __syncthreads();
    int base = (w > 0 ? warpsums[w - 1] : 0) + (v - s);
    int run = base;
    for (int i = start; i < end; i++) {
        g_off[i] = run;
        g_cursor[i] = run;
        run += g_deg[i];
    }
    if (tid == 1023) g_off[N_NODES] = run;
}

__global__ void bin_kernel(const int* __restrict__ ei) {
    int e = blockIdx.x * blockDim.x + threadIdx.x;
    if (e >= NE) return;
    int s = ei[e];
    int d = ei[NE + e];
    int pos = atomicAdd(&g_cursor[d], 1);
    g_srcs[pos] = s;
}

// parallel boundary scan over sorted batch -> g_goff (lower_bound table)
__global__ void batch_off_kernel(const int* __restrict__ batch) {
    int i = blockIdx.x * blockDim.x + threadIdx.x;
    if (i >= N_NODES) return;
    int b1 = batch[i];
    int b0 = (i == 0) ? -1 : batch[i - 1];
    for (int g = b0 + 1; g <= b1; g++) g_goff[g] = i;
    if (i == N_NODES - 1)
        for (int g = b1 + 1; g <= NGRAPH; g++) g_goff[g] = N_NODES;
}

// ====== aggregate (fp16 u64 gather): agg[n] = xh[n] + sum xh[src] ======
// one warp per node; lane owns 1 u64 = 4 cols; 8-way unrolled main loop
// (explicit index batch -> 8 independent LDG.64), 4/2/1 remainder cascade.
__global__ void __launch_bounds__(256) aggregate_kernel(float* __restrict__ agg) {
    unsigned long long tid =
        (unsigned long long)blockIdx.x * blockDim.x + threadIdx.x;
    unsigned node = (unsigned)(tid >> 5);
    if (node >= N_NODES) return;
    unsigned lane = (unsigned)tid & 31u;

    const unsigned long long* X = g_xh2;   // 32 u64 per row
    float4 sa = make_float4(0.f, 0.f, 0.f, 0.f);
    float4 sb = make_float4(0.f, 0.f, 0.f, 0.f);
    acc4h(sa, __ldg(X + (size_t)node * 32 + lane));   // self term
    int e = g_off[node];
    const int e1 = g_off[node + 1];
    for (; e + 7 < e1; e += 8) {
        int i0 = g_srcs[e];
        int i1 = g_srcs[e + 1];
        int i2 = g_srcs[e + 2];
        int i3 = g_srcs[e + 3];
        int i4 = g_srcs[e + 4];
        int i5 = g_srcs[e + 5];
        int i6 = g_srcs[e + 6];
        int i7 = g_srcs[e + 7];
        unsigned long long v0 = __ldg(X + (size_t)i0 * 32 + lane);
        unsigned long long v1 = __ldg(X + (size_t)i1 * 32 + lane);
        unsigned long long v2 = __ldg(X + (size_t)i2 * 32 + lane);
        unsigned long long v3 = __ldg(X + (size_t)i3 * 32 + lane);
        unsigned long long v4 = __ldg(X + (size_t)i4 * 32 + lane);
        unsigned long long v5 = __ldg(X + (size_t)i5 * 32 + lane);
        unsigned long long v6 = __ldg(X + (size_t)i6 * 32 + lane);
        unsigned long long v7 = __ldg(X + (size_t)i7 * 32 + lane);
        acc4h(sa, v0); acc4h(sb, v1); acc4h(sa, v2); acc4h(sb, v3);
        acc4h(sa, v4); acc4h(sb, v5); acc4h(sa, v6); acc4h(sb, v7);
    }
    if (e + 3 < e1) {
        int i0 = g_srcs[e];
        int i1 = g_srcs[e + 1];
        int i2 = g_srcs[e + 2];
        int i3 = g_srcs[e + 3];
        unsigned long long v0 = __ldg(X + (size_t)i0 * 32 + lane);
        unsigned long long v1 = __ldg(X + (size_t)i1 * 32 + lane);
        unsigned long long v2 = __ldg(X + (size_t)i2 * 32 + lane);
        unsigned long long v3 = __ldg(X + (size_t)i3 * 32 + lane);
        acc4h(sa, v0); acc4h(sb, v1); acc4h(sa, v2); acc4h(sb, v3);
        e += 4;
    }
    if (e + 1 < e1) {
        int i0 = g_srcs[e];
        int i1 = g_srcs[e + 1];
        unsigned long long v0 = __ldg(X + (size_t)i0 * 32 + lane);
        unsigned long long v1 = __ldg(X + (size_t)i1 * 32 + lane);
        acc4h(sa, v0); acc4h(sb, v1);
        e += 2;
    }
    if (e < e1) {
        unsigned long long v0 = __ldg(X + (size_t)g_srcs[e] * 32 + lane);
        acc4h(sa, v0);
    }
    sa.x += sb.x; sa.y += sb.y; sa.z += sb.z; sa.w += sb.w;
    reinterpret_cast<float4*>(agg + (size_t)node * HDIM)[lane] = sa;
}

// ============ pooling: contiguous segment sum (batch is sorted) ============
__global__ void pool_csr_kernel(const float* __restrict__ h) {
    int g = blockIdx.x;
    int c = threadIdx.x;
    int r = g_goff[g];
    const int r1 = g_goff[g + 1];
    float s0 = 0.f, s1 = 0.f;
    for (; r + 1 < r1; r += 2) {
        s0 += __ldg(h + (size_t)r * HDIM + c);
        s1 += __ldg(h + (size_t)(r + 1) * HDIM + c);
    }
    if (r < r1) s0 += __ldg(h + (size_t)r * HDIM + c);
    g_pooled[g * HDIM + c] = s0 + s1;
}

// ---------------- fused GEMM (col-pair f32x2, W in smem) ----------------
// MODE 0: t = A @ W + b ; accumulate col sum/sumsq
// MODE 1: h = relu( relu(A*scale+shift) @ W + b ) ; WH=1 also writes fp16 h
constexpr int WARPS = 8;
constexpr int RPW = 8;
constexpr int RPB = WARPS * RPW;     // 64 rows per block
constexpr int SMEM_FLOATS = HDIM * HDIM + WARPS * RPW * HDIM + WARPS * HDIM;
constexpr size_t SMEM_BYTES = SMEM_FLOATS * sizeof(float);  // 102400

template <int MODE, int WH>
__global__ void __launch_bounds__(256, 2) gemm_kernel(
    const float* __restrict__ A,
    const float* __restrict__ W, const float* __restrict__ bias,
    float* __restrict__ outp,
    float* __restrict__ colsum, float* __restrict__ colsumsq) {
    extern __shared__ float smem[];
    float* Wsm = smem;
    float* rowbuf = smem + HDIM * HDIM;
    float* redbuf = rowbuf + WARPS * RPW * HDIM;

    const int tid = threadIdx.x;
    const int w = tid >> 5;
    const int lane = tid & 31;

    {
        const float4* Wg4 = reinterpret_cast<const float4*>(W);
        float4* Ws4 = reinterpret_cast<float4*>(Wsm);
#pragma unroll
        for (int i = 0; i < (HDIM * HDIM / 4) / 256; i++)
            Ws4[i * 256 + tid] = __ldg(Wg4 + i * 256 + tid);
    }

    const float4 bias4 = __ldg(reinterpret_cast<const float4*>(bias) + lane);
    float4 sc4 = make_float4(0.f, 0.f, 0.f, 0.f), sh4 = sc4;
    if (MODE == 1) {
        sc4 = *(reinterpret_cast<const float4*>(g_scale) + lane);
        sh4 = *(reinterpret_cast<const float4*>(g_shift) + lane);
    }

    float* rb = rowbuf + w * (RPW * HDIM);
    const int rbase = blockIdx.x * RPB + w * RPW;

#pragma unroll
    for (int r = 0; r < RPW; r++) {
        int row = rbase + r;
        int rr = row < N_NODES ? row : N_NODES - 1;
        float4 a = __ldg(reinterpret_cast<const float4*>(A + (size_t)rr * HDIM) + lane);
        if (MODE == 1) {
            a.x = fmaxf(fmaf(a.x, sc4.x, sh4.x), 0.f);
            a.y = fmaxf(fmaf(a.y, sc4.y, sh4.y), 0.f);
            a.z = fmaxf(fmaf(a.z, sc4.z, sh4.z), 0.f);
            a.w = fmaxf(fmaf(a.w, sc4.w, sh4.w), 0.f);
        }
        reinterpret_cast<float4*>(rb + r * HDIM)[lane] = a;
    }
    __syncthreads();

    unsigned long long accL[RPW], accH[RPW];
    {
        unsigned long long blo, bhi;
        PACK2F(blo, bias4.x, bias4.y);
        PACK2F(bhi, bias4.z, bias4.w);
#pragma unroll
        for (int r = 0; r < RPW; r++) { accL[r] = blo; accH[r] = bhi; }
    }

    const float4* Ws4 = reinterpret_cast<const float4*>(Wsm);
#pragma unroll 4
    for (int k0 = 0; k0 < HDIM / 4; k0++) {
        float4 av[RPW];
#pragma unroll
        for (int r = 0; r < RPW; r++)
            av[r] = reinterpret_cast<const float4*>(rb + r * HDIM)[k0];
#pragma unroll
        for (int s4 = 0; s4 < 4; s4++) {
            const float4 wv = Ws4[(4 * k0 + s4) * 32 + lane];
            unsigned long long wlo, whi;
            PACK2F(wlo, wv.x, wv.y);
            PACK2F(whi, wv.z, wv.w);
#pragma unroll
            for (int r = 0; r < RPW; r++) {
                const float a = (s4 == 0) ? av[r].x
                              : (s4 == 1) ? av[r].y
                              : (s4 == 2) ? av[r].z : av[r].w;
                unsigned long long a2;
                PACK2F(a2, a, a);
                FFMA2(accL[r], a2, wlo, accL[r]);
                FFMA2(accH[r], a2, whi, accH[r]);
            }
        }
    }

    float s0 = 0.f, s1 = 0.f, s2 = 0.f, s3 = 0.f;
    float q0 = 0.f, q1 = 0.f, q2 = 0.f, q3 = 0.f;
#pragma unroll
    for (int r = 0; r < RPW; r++) {
        int row = rbase + r;
        if (row < N_NODES) {
            float4 c;
            UNPACK2F(c.x, c.y, accL[r]);
            UNPACK2F(c.z, c.w, accH[r]);
            if (MODE == 1) {
                c.x = fmaxf(c.x, 0.f); c.y = fmaxf(c.y, 0.f);
                c.z = fmaxf(c.z, 0.f); c.w = fmaxf(c.w, 0.f);
            }
            reinterpret_cast<float4*>(outp + (size_t)row * HDIM)[lane] = c;
            if (WH)
                g_xh2[(size_t)row * 32 + lane] = pack4h(c);
            if (MODE == 0) {
                s0 += c.x; s1 += c.y; s2 += c.z; s3 += c.w;
                q0 += c.x * c.x; q1 += c.y * c.y;
                q2 += c.z * c.z; q3 += c.w * c.w;
            }
        }
    }

    if (MODE == 0) {
        float* rw = redbuf + w * HDIM + 4 * lane;
        rw[0] = s0; rw[1] = s1; rw[2] = s2; rw[3] = s3;
        __syncthreads();
        if (tid < HDIM) {
            float t = 0.f;
#pragma unroll
            for (int ww = 0; ww < WARPS; ww++) t += redbuf[ww * HDIM + tid];
            atomicAdd(&colsum[tid], t);
        }
        __syncthreads();
        rw[0] = q0; rw[1] = q1; rw[2] = q2; rw[3] = q3;
        __syncthreads();
        if (tid < HDIM) {
            float t = 0.f;
#pragma unroll
            for (int ww = 0; ww < WARPS; ww++) t += redbuf[ww * HDIM + tid];
            atomicAdd(&colsumsq[tid], t);
        }
    }
}

// ---------------- BN finalize ----------------
__global__ void bn_finalize(const float* __restrict__ gamma,
                            const float* __restrict__ beta) {
    int i = threadIdx.x;
    const float invn = 1.0f / (float)N_NODES;
    float m = g_colsum[i] * invn;
    float v = g_colsumsq[i] * invn - m * m;
    float istd = rsqrtf(v + 1e-5f);
    float sc = istd * gamma[i];
    g_scale[i] = sc;
    g_shift[i] = beta[i] - m * sc;
}

// ---------------- classifier ----------------
__global__ void final_kernel(const float* __restrict__ Wl,
                             const float* __restrict__ bl,
                             float* __restrict__ out) {
    int g = blockIdx.x * blockDim.x + threadIdx.x;
    if (g >= NGRAPH) return;
    float acc[TDIM];
#pragma unroll
    for (int t = 0; t < TDIM; t++) acc[t] = __ldg(&bl[t]);
    const float* p = g_pooled + (size_t)g * HDIM;
#pragma unroll 8
    for (int k = 0; k < HDIM; k++) {
        float pv = p[k];
#pragma unroll
        for (int t = 0; t < TDIM; t++)
            acc[t] = fmaf(pv, __ldg(&Wl[k * TDIM + t]), acc[t]);
    }
#pragma unroll
    for (int t = 0; t < TDIM; t++) out[g * TDIM + t] = acc[t];
}

// ---------------- launch ----------------
extern "C" void kernel_launch(void* const* d_in, const int* in_sizes, int n_in,
                              void* d_out, int out_size) {
    const float* x = (const float*)d_in[0];
    const int* ei = (const int*)d_in[1];
    const int* batch = (const int*)d_in[2];
    const float* W1a = (const float*)d_in[3];
    const float* b1a = (const float*)d_in[4];
    const float* g1  = (const float*)d_in[5];
    const float* bt1 = (const float*)d_in[6];
    const float* W1b = (const float*)d_in[7];
    const float* b1b = (const float*)d_in[8];
    const float* W2a = (const float*)d_in[9];
    const float* b2a = (const float*)d_in[10];
    const float* g2  = (const float*)d_in[11];
    const float* bt2 = (const float*)d_in[12];
    const float* W2b = (const float*)d_in[13];
    const float* b2b = (const float*)d_in[14];
    const float* Wl  = (const float*)d_in[15];
    const float* bl  = (const float*)d_in[16];
    float* out = (float*)d_out;

    float *aggp, *tp, *hp, *csp, *cqp;
    int* degp;
    cudaGetSymbolAddress((void**)&aggp, g_agg);
    cudaGetSymbolAddress((void**)&tp, g_t);
    cudaGetSymbolAddress((void**)&hp, g_h);
    cudaGetSymbolAddress((void**)&csp, g_colsum);
    cudaGetSymbolAddress((void**)&cqp, g_colsumsq);
    cudaGetSymbolAddress((void**)&degp, g_deg);

    cudaFuncSetAttribute(gemm_kernel<0, 0>,
                         cudaFuncAttributeMaxDynamicSharedMemorySize,
                         (int)SMEM_BYTES);
    cudaFuncSetAttribute(gemm_kernel<1, 0>,
                         cudaFuncAttributeMaxDynamicSharedMemorySize,
                         (int)SMEM_BYTES);
    cudaFuncSetAttribute(gemm_kernel<1, 1>,
                         cudaFuncAttributeMaxDynamicSharedMemorySize,
                         (int)SMEM_BYTES);

    const int EDGE_BLOCKS = (NE + 255) / 256;
    const int NODE_BLOCKS = (N_NODES + 255) / 256;
    const int AGG_BLOCKS = (int)(((long long)N_NODES * 32 + 255) / 256);
    const int CONV_BLOCKS = (int)(((size_t)N_NODES * (HDIM / 4) + 255) / 256);
    const int GEMM_BLOCKS = (N_NODES + RPB - 1) / RPB;  // 1563

    // ---- fp16 operand + CSR build ----
    tohalf_kernel<<<CONV_BLOCKS, 256>>>(x);
    cudaMemsetAsync(degp, 0, N_NODES * sizeof(int));
    hist_kernel<<<EDGE_BLOCKS, 256>>>(ei);
    scan_kernel<<<1, 1024>>>();
    bin_kernel<<<EDGE_BLOCKS, 256>>>(ei);
    batch_off_kernel<<<NODE_BLOCKS, 256>>>(batch);

    // ---- GIN layer 1 ----
    aggregate_kernel<<<AGG_BLOCKS, 256>>>(aggp);
    cudaMemsetAsync(csp, 0, HDIM * sizeof(float));
    cudaMemsetAsync(cqp, 0, HDIM * sizeof(float));
    gemm_kernel<0, 0><<<GEMM_BLOCKS, 256, SMEM_BYTES>>>(aggp, W1a, b1a, tp, csp, cqp);
    bn_finalize<<<1, HDIM>>>(g1, bt1);
    gemm_kernel<1, 1><<<GEMM_BLOCKS, 256, SMEM_BYTES>>>(tp, W1b, b1b, hp, nullptr, nullptr);

    // ---- GIN layer 2 (aggregate reads fp16 h written by gemm<1,1>) ----
    aggregate_kernel<<<AGG_BLOCKS, 256>>>(aggp);
    cudaMemsetAsync(csp, 0, HDIM * sizeof(float));
    cudaMemsetAsync(cqp, 0, HDIM * sizeof(float));
    gemm_kernel<0, 0><<<GEMM_BLOCKS, 256, SMEM_BYTES>>>(aggp, W2a, b2a, tp, csp, cqp);
    bn_finalize<<<1, HDIM>>>(g2, bt2);
    gemm_kernel<1, 0><<<GEMM_BLOCKS, 256, SMEM_BYTES>>>(tp, W2b, b2b, hp, nullptr, nullptr);

    // ---- pool + classifier ----
    pool_csr_kernel<<<NGRAPH, HDIM>>>(hp);
    final_kernel<<<(NGRAPH + 255) / 256, 256>>>(Wl, bl, out);
}